// round 12
// baseline (speedup 1.0000x reference)
#include <cuda_runtime.h>
#include <cuda_fp16.h>
#include <mma.h>
#include <math.h>

using namespace nvcuda;

#define NN 100000
#define NPAD (NN + 128)
#define EE 1600000
#define EWSZ (EE + 4 * NN + 8)
#define F  128
#define G  64
#define CHUNK 512
#define NBLK ((NN + CHUNK - 1) / CHUNK)   // 196
#define PCHUNK 32
#define WSTRH 136
#define ASTRH 136

// smem: sW (fp16 W) + A tile 128 rows; no C bounce (direct fp16 frag store)
#define SW_BYTES (128 * WSTRH * 2)            // 34816
#define SA_BYTES (128 * ASTRH * 2)            // 34816
#define SMEM_TOTAL (SW_BYTES + SA_BYTES)      // 69632 -> 3 blocks/SM

// ---------------- device scratch (allocation-free) ----------------
__device__ __half g_half[NPAD * F];  // hl = h @ W, fp16
__device__ __half g_hin[NPAD * F];   // relu(agg) output, fp16
__device__ float  g_dinv[NN];
__device__ int    g_cnt[NN];
__device__ int    g_cur[NN];
__device__ int    g_off[NN + 1];
__device__ int2   g_ew[EWSZ];        // {src, norm weight bits}, padded + guard
__device__ int    g_bsum[NBLK];
__device__ int    g_bpre[NBLK];
__device__ float  g_pooled[G * F];

// ---------------- setup: degree, dinv, padded CSR ----------------
__global__ void k_zero() {
    int i = blockIdx.x * blockDim.x + threadIdx.x;
    if (i < NN) { g_cnt[i] = 0; g_cur[i] = 0; }
    if (i < G * F) g_pooled[i] = 0.f;
}

__global__ void k_count(const int* __restrict__ dst, int e) {
    int i = blockIdx.x * blockDim.x + threadIdx.x;
    if (i < e) atomicAdd(&g_cnt[dst[i]], 1);
}

__global__ void k_scan1(int n) {
    __shared__ int s[CHUNK];
    int t = threadIdx.x;
    int idx = blockIdx.x * CHUNK + t;
    int c = (idx < n) ? g_cnt[idx] : 0;
    if (idx < n) g_dinv[idx] = rsqrtf((float)(c + 1));   // +1 self loop
    s[t] = (c + 3) & ~3;                                 // padded to mult of 4
    __syncthreads();
    for (int o = CHUNK / 2; o > 0; o >>= 1) {
        if (t < o) s[t] += s[t + o];
        __syncthreads();
    }
    if (t == 0) g_bsum[blockIdx.x] = s[0];
}

__global__ void k_scan2(int n) {
    __shared__ int s[256];
    int t = threadIdx.x;
    int v = (t < NBLK) ? g_bsum[t] : 0;
    s[t] = v;
    __syncthreads();
    for (int o = 1; o < 256; o <<= 1) {
        int x = (t >= o) ? s[t - o] : 0;
        __syncthreads();
        s[t] += x;
        __syncthreads();
    }
    if (t < NBLK) g_bpre[t] = s[t] - v;
    if (t == 255) {
        g_off[n] = s[255];
        #pragma unroll
        for (int i = 0; i < 8; i++) g_ew[s[255] + i] = make_int2(0, 0);  // guard
    }
}

// scan3 also writes the per-node pad entries (disjoint from k_fill's region)
__global__ void k_scan3(int n) {
    __shared__ int s[CHUNK];
    int t = threadIdx.x;
    int idx = blockIdx.x * CHUNK + t;
    int cnt = (idx < n) ? g_cnt[idx] : 0;
    int v = (cnt + 3) & ~3;
    s[t] = v;
    __syncthreads();
    for (int o = 1; o < CHUNK; o <<= 1) {
        int x = (t >= o) ? s[t - o] : 0;
        __syncthreads();
        s[t] += x;
        __syncthreads();
    }
    if (idx < n) {
        int off = g_bpre[blockIdx.x] + s[t] - v;   // exclusive
        g_off[idx] = off;
        for (int p = off + cnt; p < off + v; p++) g_ew[p] = make_int2(0, 0);
    }
}

__global__ void k_fill(const int* __restrict__ src, const int* __restrict__ dst, int e) {
    int i = blockIdx.x * blockDim.x + threadIdx.x;
    if (i < e) {
        int d = dst[i];
        int s = src[i];
        int p = atomicAdd(&g_cur[d], 1);
        float w = g_dinv[s] * g_dinv[d];
        g_ew[g_off[d] + p] = make_int2(s, __float_as_int(w));
    }
}

// ---------------- GEMM (fp16 HMMA, fp16 acc): g_half = in @ W ----------------
// Block tile 128x128, 8 warps (4x2), warp tile 32x64. fp16 accumulators are
// stored DIRECTLY to g_half via store_matrix_sync (no smem C bounce, 2 syncs/tile).
__global__ __launch_bounds__(256, 3)
void k_gemm_h(const float* __restrict__ xin, const float* __restrict__ W,
              int n, int first) {
    extern __shared__ char smraw[];
    __half* sW = (__half*)smraw;
    __half* sA = (__half*)(smraw + SW_BYTES);
    int t = threadIdx.x;

    for (int i = t * 2; i < F * F; i += 256 * 2) {
        int k = i >> 7, f = i & 127;
        __half2 h = __floats2half2_rn(W[i], W[i + 1]);
        *(__half2*)&sW[k * WSTRH + f] = h;
    }

    int warp = t >> 5;
    int wr = (warp & 3) * 32;      // 4 row groups of 32
    int wc = (warp >> 2) * 64;     // 2 col groups of 64
    int ntiles = (n + 127) >> 7;

    for (int tile = blockIdx.x; tile < ntiles; tile += gridDim.x) {
        int row0 = tile << 7;
        __syncthreads();           // protect sA reuse (and first-pass sW)
        if (first) {
            for (int i = t * 8; i < 128 * F; i += 256 * 8) {
                int r = i >> 7, k = i & 127;
                int rr = row0 + r;
                float4 v0 = make_float4(0.f, 0.f, 0.f, 0.f), v1 = v0;
                if (rr < n) {
                    v0 = *(const float4*)&xin[rr * F + k];
                    v1 = *(const float4*)&xin[rr * F + k + 4];
                }
                __half2 h0 = __floats2half2_rn(v0.x, v0.y);
                __half2 h1 = __floats2half2_rn(v0.z, v0.w);
                __half2 h2 = __floats2half2_rn(v1.x, v1.y);
                __half2 h3 = __floats2half2_rn(v1.z, v1.w);
                uint4 u;
                u.x = *reinterpret_cast<unsigned*>(&h0);
                u.y = *reinterpret_cast<unsigned*>(&h1);
                u.z = *reinterpret_cast<unsigned*>(&h2);
                u.w = *reinterpret_cast<unsigned*>(&h3);
                *(uint4*)&sA[r * ASTRH + k] = u;
            }
        } else {
            // g_hin is NPAD-padded (NN+128): unguarded vector loads are safe
            for (int i = t * 8; i < 128 * F; i += 256 * 8) {
                int r = i >> 7, k = i & 127;
                uint4 u = *(const uint4*)&g_hin[(row0 + r) * F + k];
                *(uint4*)&sA[r * ASTRH + k] = u;
            }
        }
        __syncthreads();

        wmma::fragment<wmma::accumulator, 16, 16, 16, __half> c[2][4];
        #pragma unroll
        for (int i = 0; i < 2; i++)
            #pragma unroll
            for (int j = 0; j < 4; j++)
                wmma::fill_fragment(c[i][j], __float2half(0.f));

        #pragma unroll
        for (int k0 = 0; k0 < F; k0 += 16) {
            wmma::fragment<wmma::matrix_a, 16, 16, 16, __half, wmma::row_major> a0, a1;
            wmma::fragment<wmma::matrix_b, 16, 16, 16, __half, wmma::row_major> b[4];
            wmma::load_matrix_sync(a0, &sA[wr * ASTRH + k0], ASTRH);
            wmma::load_matrix_sync(a1, &sA[(wr + 16) * ASTRH + k0], ASTRH);
            #pragma unroll
            for (int j = 0; j < 4; j++)
                wmma::load_matrix_sync(b[j], &sW[k0 * WSTRH + wc + 16 * j], WSTRH);
            #pragma unroll
            for (int j = 0; j < 4; j++) {
                wmma::mma_sync(c[0][j], a0, b[j], c[0][j]);
                wmma::mma_sync(c[1][j], a1, b[j], c[1][j]);
            }
        }

        // direct fp16 store to global (g_half padded to NPAD: unguarded OK)
        #pragma unroll
        for (int i = 0; i < 2; i++)
            #pragma unroll
            for (int j = 0; j < 4; j++)
                wmma::store_matrix_sync(&g_half[(row0 + wr + 16 * i) * F + wc + 16 * j],
                                        c[i][j], F, wmma::mem_row_major);
    }
}

// ---------------- Aggregation (software-pipelined, padded batches of 4) ----
__global__ void k_agg(const float* __restrict__ bias, int n) {
    int tid = blockIdx.x * blockDim.x + threadIdx.x;
    int hw = tid >> 4;
    int lane = tid & 15;
    int nhw = (gridDim.x * blockDim.x) >> 4;
    int fo = lane * 8;
    const __half* hl = g_half;
    const float4 bl = *(const float4*)&bias[fo];
    const float4 bh = *(const float4*)&bias[fo + 4];

    for (int nd = hw; nd < n; nd += nhw) {
        float dn = g_dinv[nd];
        float sw = dn * dn;
        float acc[8];
        {
            uint4 u = *(const uint4*)&hl[nd * F + fo];
            float2 p0 = __half22float2(*reinterpret_cast<__half2*>(&u.x));
            float2 p1 = __half22float2(*reinterpret_cast<__half2*>(&u.y));
            float2 p2 = __half22float2(*reinterpret_cast<__half2*>(&u.z));
            float2 p3 = __half22float2(*reinterpret_cast<__half2*>(&u.w));
            acc[0] = p0.x * sw; acc[1] = p0.y * sw;
            acc[2] = p1.x * sw; acc[3] = p1.y * sw;
            acc[4] = p2.x * sw; acc[5] = p2.y * sw;
            acc[6] = p3.x * sw; acc[7] = p3.y * sw;
        }
        int i = g_off[nd], iend = g_off[nd + 1];
        if (i < iend) {
            int2 e0 = g_ew[i], e1 = g_ew[i + 1], e2 = g_ew[i + 2], e3 = g_ew[i + 3];
            while (true) {
                uint4 u0 = *(const uint4*)&hl[e0.x * F + fo];
                uint4 u1 = *(const uint4*)&hl[e1.x * F + fo];
                uint4 u2 = *(const uint4*)&hl[e2.x * F + fo];
                uint4 u3 = *(const uint4*)&hl[e3.x * F + fo];
                i += 4;
                int2 f0 = g_ew[i], f1 = g_ew[i + 1], f2 = g_ew[i + 2], f3 = g_ew[i + 3];
                float w0 = __int_as_float(e0.y), w1 = __int_as_float(e1.y);
                float w2 = __int_as_float(e2.y), w3 = __int_as_float(e3.y);
                float2 a0 = __half22float2(*reinterpret_cast<__half2*>(&u0.x));
                float2 a1 = __half22float2(*reinterpret_cast<__half2*>(&u0.y));
                float2 a2 = __half22float2(*reinterpret_cast<__half2*>(&u0.z));
                float2 a3 = __half22float2(*reinterpret_cast<__half2*>(&u0.w));
                acc[0] = fmaf(a0.x, w0, acc[0]); acc[1] = fmaf(a0.y, w0, acc[1]);
                acc[2] = fmaf(a1.x, w0, acc[2]); acc[3] = fmaf(a1.y, w0, acc[3]);
                acc[4] = fmaf(a2.x, w0, acc[4]); acc[5] = fmaf(a2.y, w0, acc[5]);
                acc[6] = fmaf(a3.x, w0, acc[6]); acc[7] = fmaf(a3.y, w0, acc[7]);
                a0 = __half22float2(*reinterpret_cast<__half2*>(&u1.x));
                a1 = __half22float2(*reinterpret_cast<__half2*>(&u1.y));
                a2 = __half22float2(*reinterpret_cast<__half2*>(&u1.z));
                a3 = __half22float2(*reinterpret_cast<__half2*>(&u1.w));
                acc[0] = fmaf(a0.x, w1, acc[0]); acc[1] = fmaf(a0.y, w1, acc[1]);
                acc[2] = fmaf(a1.x, w1, acc[2]); acc[3] = fmaf(a1.y, w1, acc[3]);
                acc[4] = fmaf(a2.x, w1, acc[4]); acc[5] = fmaf(a2.y, w1, acc[5]);
                acc[6] = fmaf(a3.x, w1, acc[6]); acc[7] = fmaf(a3.y, w1, acc[7]);
                a0 = __half22float2(*reinterpret_cast<__half2*>(&u2.x));
                a1 = __half22float2(*reinterpret_cast<__half2*>(&u2.y));
                a2 = __half22float2(*reinterpret_cast<__half2*>(&u2.z));
                a3 = __half22float2(*reinterpret_cast<__half2*>(&u2.w));
                acc[0] = fmaf(a0.x, w2, acc[0]); acc[1] = fmaf(a0.y, w2, acc[1]);
                acc[2] = fmaf(a1.x, w2, acc[2]); acc[3] = fmaf(a1.y, w2, acc[3]);
                acc[4] = fmaf(a2.x, w2, acc[4]); acc[5] = fmaf(a2.y, w2, acc[5]);
                acc[6] = fmaf(a3.x, w2, acc[6]); acc[7] = fmaf(a3.y, w2, acc[7]);
                a0 = __half22float2(*reinterpret_cast<__half2*>(&u3.x));
                a1 = __half22float2(*reinterpret_cast<__half2*>(&u3.y));
                a2 = __half22float2(*reinterpret_cast<__half2*>(&u3.z));
                a3 = __half22float2(*reinterpret_cast<__half2*>(&u3.w));
                acc[0] = fmaf(a0.x, w3, acc[0]); acc[1] = fmaf(a0.y, w3, acc[1]);
                acc[2] = fmaf(a1.x, w3, acc[2]); acc[3] = fmaf(a1.y, w3, acc[3]);
                acc[4] = fmaf(a2.x, w3, acc[4]); acc[5] = fmaf(a2.y, w3, acc[5]);
                acc[6] = fmaf(a3.x, w3, acc[6]); acc[7] = fmaf(a3.y, w3, acc[7]);
                if (i >= iend) break;
                e0 = f0; e1 = f1; e2 = f2; e3 = f3;
            }
        }
        acc[0] = fmaxf(acc[0] + bl.x, 0.f); acc[1] = fmaxf(acc[1] + bl.y, 0.f);
        acc[2] = fmaxf(acc[2] + bl.z, 0.f); acc[3] = fmaxf(acc[3] + bl.w, 0.f);
        acc[4] = fmaxf(acc[4] + bh.x, 0.f); acc[5] = fmaxf(acc[5] + bh.y, 0.f);
        acc[6] = fmaxf(acc[6] + bh.z, 0.f); acc[7] = fmaxf(acc[7] + bh.w, 0.f);
        __half2 h0 = __floats2half2_rn(acc[0], acc[1]);
        __half2 h1 = __floats2half2_rn(acc[2], acc[3]);
        __half2 h2 = __floats2half2_rn(acc[4], acc[5]);
        __half2 h3 = __floats2half2_rn(acc[6], acc[7]);
        uint4 o;
        o.x = *reinterpret_cast<unsigned*>(&h0);
        o.y = *reinterpret_cast<unsigned*>(&h1);
        o.z = *reinterpret_cast<unsigned*>(&h2);
        o.w = *reinterpret_cast<unsigned*>(&h3);
        *(uint4*)&g_hin[nd * F + fo] = o;
    }
}

// ---------------- Pooling: 32 nodes per block --------
__global__ void k_pool(const int* __restrict__ batch, int n) {
    int f = threadIdx.x;
    int n0 = blockIdx.x * PCHUNK;
    if (n0 >= n) return;
    int n1 = min(n0 + PCHUNK, n);
    int cur = batch[n0];
    float m = 0.f;
    for (int nd = n0; nd < n1; nd++) {
        int gg = batch[nd];
        if (gg != cur) {
            atomicMax((int*)&g_pooled[cur * F + f], __float_as_int(m));
            cur = gg;
            m = 0.f;
        }
        m = fmaxf(m, __half2float(g_hin[nd * F + f]));
    }
    atomicMax((int*)&g_pooled[cur * F + f], __float_as_int(m));
}

// ---------------- Head ----------------
__global__ void k_head(const float* __restrict__ Wp1, const float* __restrict__ bp1,
                       const float* __restrict__ Wp2, const float* __restrict__ bp2,
                       float* __restrict__ out) {
    __shared__ float sp[F];
    __shared__ float t1[F];
    int t = threadIdx.x, g = blockIdx.x;
    sp[t] = g_pooled[g * F + t];
    __syncthreads();
    float a = bp1[t];
    #pragma unroll 4
    for (int k = 0; k < F; k++) a = fmaf(sp[k], Wp1[k * F + t], a);
    t1[t] = a;
    __syncthreads();
    if (t == 0) {
        float l0 = bp2[0], l1 = bp2[1];
        for (int k = 0; k < F; k++) {
            l0 = fmaf(t1[k], Wp2[2 * k], l0);
            l1 = fmaf(t1[k], Wp2[2 * k + 1], l1);
        }
        float m = fmaxf(l0, l1);
        float lse = m + logf(expf(l0 - m) + expf(l1 - m));
        out[2 * g] = l0 - lse;
        out[2 * g + 1] = l1 - lse;
    }
}

// ---------------- launch ----------------
extern "C" void kernel_launch(void* const* d_in, const int* in_sizes, int n_in,
                              void* d_out, int out_size) {
    const float* x   = (const float*)d_in[0];
    const int*   ei  = (const int*)d_in[1];
    const int*   bat = (const int*)d_in[2];
    const float* W1  = (const float*)d_in[3];  const float* b1  = (const float*)d_in[4];
    const float* W2  = (const float*)d_in[5];  const float* b2  = (const float*)d_in[6];
    const float* W3  = (const float*)d_in[7];  const float* b3  = (const float*)d_in[8];
    const float* Wp1 = (const float*)d_in[9];  const float* bp1 = (const float*)d_in[10];
    const float* Wp2 = (const float*)d_in[11]; const float* bp2 = (const float*)d_in[12];
    float* out = (float*)d_out;

    int n = in_sizes[0] / F;        // 100000
    int e = in_sizes[1] / 2;        // 1600000
    const int* src = ei;
    const int* dst = ei + e;

    cudaFuncSetAttribute(k_gemm_h, cudaFuncAttributeMaxDynamicSharedMemorySize, SMEM_TOTAL);

    k_zero<<<(NN + 255) / 256, 256>>>();                   // idx 0
    k_count<<<(e + 255) / 256, 256>>>(dst, e);             // idx 1
    k_scan1<<<NBLK, CHUNK>>>(n);                           // idx 2
    k_gemm_h<<<444, 256, SMEM_TOTAL>>>(x, W1, n, 1);       // idx 3 <-- profiler target
    k_scan2<<<1, 256>>>(n);                                // idx 4
    k_scan3<<<NBLK, CHUNK>>>(n);                           // idx 5 (+pad)
    k_fill<<<(e + 255) / 256, 256>>>(src, dst, e);         // idx 6

    k_agg<<<1184, 256>>>(b1, n);
    k_gemm_h<<<444, 256, SMEM_TOTAL>>>(x, W2, n, 0);
    k_agg<<<1184, 256>>>(b2, n);
    k_gemm_h<<<444, 256, SMEM_TOTAL>>>(x, W3, n, 0);
    k_agg<<<1184, 256>>>(b3, n);

    k_pool<<<(n + PCHUNK - 1) / PCHUNK, F>>>(bat, n);
    k_head<<<G, F>>>(Wp1, bp1, Wp2, bp2, out);
}

// round 15
// speedup vs baseline: 1.0141x; 1.0141x over previous
#include <cuda_runtime.h>
#include <cuda_fp16.h>
#include <mma.h>
#include <math.h>

using namespace nvcuda;

#define NN 100000
#define NPAD (NN + 128)
#define EE 1600000
#define EWSZ (EE + 4 * NN + 8)
#define F  128
#define G  64
#define CHUNK 512
#define NBLK ((NN + CHUNK - 1) / CHUNK)   // 196
#define PCHUNK 32
#define WSTRH 136
#define ASTRH 136
#define CSTR  132

#define SW_BYTES (128 * WSTRH * 2)            // 34816
#define SA_BYTES (128 * ASTRH * 2)            // 34816
#define SMEM_TOTAL (SW_BYTES + SA_BYTES)      // 69632

// ---------------- device scratch (allocation-free) ----------------
__device__ __half g_half[NPAD * F];  // hl = h @ W, fp16
__device__ __half g_hin[NPAD * F];   // relu(agg) output, fp16
__device__ float  g_dinv[NN];
__device__ int    g_cnt[NN];
__device__ int    g_cur[NN];
__device__ int    g_off[NN + 1];
__device__ int2   g_ew[EWSZ];        // {src, norm weight bits}, padded + guard
__device__ int    g_bsum[NBLK];
__device__ int    g_bpre[NBLK];
__device__ float  g_pooled[G * F];

// ---------------- setup: degree, dinv, padded CSR ----------------
__global__ void k_zero() {
    int i = blockIdx.x * blockDim.x + threadIdx.x;
    if (i < NN) { g_cnt[i] = 0; g_cur[i] = 0; }
    if (i < G * F) g_pooled[i] = 0.f;
}

// vectorized: each thread counts 4 edges (int4 load)
__global__ void k_count(const int* __restrict__ dst, int e) {
    int i = (blockIdx.x * blockDim.x + threadIdx.x) * 4;
    if (i + 4 <= e) {
        int4 d = *(const int4*)&dst[i];
        atomicAdd(&g_cnt[d.x], 1);
        atomicAdd(&g_cnt[d.y], 1);
        atomicAdd(&g_cnt[d.z], 1);
        atomicAdd(&g_cnt[d.w], 1);
    } else {
        for (int j = i; j < e; j++) atomicAdd(&g_cnt[dst[j]], 1);
    }
}

__global__ void k_scan1(int n) {
    __shared__ int s[CHUNK];
    int t = threadIdx.x;
    int idx = blockIdx.x * CHUNK + t;
    int c = (idx < n) ? g_cnt[idx] : 0;
    if (idx < n) g_dinv[idx] = rsqrtf((float)(c + 1));   // +1 self loop
    s[t] = (c + 3) & ~3;                                 // padded to mult of 4
    __syncthreads();
    for (int o = CHUNK / 2; o > 0; o >>= 1) {
        if (t < o) s[t] += s[t + o];
        __syncthreads();
    }
    if (t == 0) g_bsum[blockIdx.x] = s[0];
}

__global__ void k_scan2(int n) {
    __shared__ int s[256];
    int t = threadIdx.x;
    int v = (t < NBLK) ? g_bsum[t] : 0;
    s[t] = v;
    __syncthreads();
    for (int o = 1; o < 256; o <<= 1) {
        int x = (t >= o) ? s[t - o] : 0;
        __syncthreads();
        s[t] += x;
        __syncthreads();
    }
    if (t < NBLK) g_bpre[t] = s[t] - v;
    if (t == 255) {
        g_off[n] = s[255];
        #pragma unroll
        for (int i = 0; i < 8; i++) g_ew[s[255] + i] = make_int2(0, 0);  // guard
    }
}

// scan3 also writes the per-node pad entries (disjoint from k_fill's region)
__global__ void k_scan3(int n) {
    __shared__ int s[CHUNK];
    int t = threadIdx.x;
    int idx = blockIdx.x * CHUNK + t;
    int cnt = (idx < n) ? g_cnt[idx] : 0;
    int v = (cnt + 3) & ~3;
    s[t] = v;
    __syncthreads();
    for (int o = 1; o < CHUNK; o <<= 1) {
        int x = (t >= o) ? s[t - o] : 0;
        __syncthreads();
        s[t] += x;
        __syncthreads();
    }
    if (idx < n) {
        int off = g_bpre[blockIdx.x] + s[t] - v;   // exclusive
        g_off[idx] = off;
        for (int p = off + cnt; p < off + v; p++) g_ew[p] = make_int2(0, 0);
    }
}

__global__ void k_fill(const int* __restrict__ src, const int* __restrict__ dst, int e) {
    int i = blockIdx.x * blockDim.x + threadIdx.x;
    if (i < e) {
        int d = dst[i];
        int s = src[i];
        int p = atomicAdd(&g_cur[d], 1);
        float w = g_dinv[s] * g_dinv[d];
        g_ew[g_off[d] + p] = make_int2(s, __float_as_int(w));
    }
}

// ---------------- GEMM (fp16 HMMA, fp32 acc): g_half = in @ W ----------------
// Block tile 128x128, 8 warps (4x2), warp tile 32x64, smem C bounce epilogue.
__global__ __launch_bounds__(256, 2)
void k_gemm_h(const float* __restrict__ xin, const float* __restrict__ W,
              int n, int first) {
    extern __shared__ char smraw[];
    __half* sW = (__half*)smraw;
    __half* sA = (__half*)(smraw + SW_BYTES);
    float*  sC = (float*)sA;       // alias, used after mainloop
    int t = threadIdx.x;

    for (int i = t * 2; i < F * F; i += 256 * 2) {
        int k = i >> 7, f = i & 127;
        __half2 h = __floats2half2_rn(W[i], W[i + 1]);
        *(__half2*)&sW[k * WSTRH + f] = h;
    }

    int warp = t >> 5;
    int wr = (warp & 3) * 32;      // 4 row groups of 32
    int wc = (warp >> 2) * 64;     // 2 col groups of 64
    int ntiles = (n + 127) >> 7;

    for (int tile = blockIdx.x; tile < ntiles; tile += gridDim.x) {
        int row0 = tile << 7;
        __syncthreads();           // protect sA/sC reuse (and first-pass sW)
        if (first) {
            for (int i = t * 8; i < 128 * F; i += 256 * 8) {
                int r = i >> 7, k = i & 127;
                int rr = row0 + r;
                float4 v0 = make_float4(0.f, 0.f, 0.f, 0.f), v1 = v0;
                if (rr < n) {
                    v0 = *(const float4*)&xin[rr * F + k];
                    v1 = *(const float4*)&xin[rr * F + k + 4];
                }
                __half2 h0 = __floats2half2_rn(v0.x, v0.y);
                __half2 h1 = __floats2half2_rn(v0.z, v0.w);
                __half2 h2 = __floats2half2_rn(v1.x, v1.y);
                __half2 h3 = __floats2half2_rn(v1.z, v1.w);
                uint4 u;
                u.x = *reinterpret_cast<unsigned*>(&h0);
                u.y = *reinterpret_cast<unsigned*>(&h1);
                u.z = *reinterpret_cast<unsigned*>(&h2);
                u.w = *reinterpret_cast<unsigned*>(&h3);
                *(uint4*)&sA[r * ASTRH + k] = u;
            }
        } else {
            // g_hin is NPAD-padded (NN+128): unguarded vector loads are safe
            for (int i = t * 8; i < 128 * F; i += 256 * 8) {
                int r = i >> 7, k = i & 127;
                uint4 u = *(const uint4*)&g_hin[(row0 + r) * F + k];
                *(uint4*)&sA[r * ASTRH + k] = u;
            }
        }
        __syncthreads();

        wmma::fragment<wmma::accumulator, 16, 16, 16, float> c[2][4];
        #pragma unroll
        for (int i = 0; i < 2; i++)
            #pragma unroll
            for (int j = 0; j < 4; j++)
                wmma::fill_fragment(c[i][j], 0.f);

        #pragma unroll
        for (int k0 = 0; k0 < F; k0 += 16) {
            wmma::fragment<wmma::matrix_a, 16, 16, 16, __half, wmma::row_major> a0, a1;
            wmma::fragment<wmma::matrix_b, 16, 16, 16, __half, wmma::row_major> b[4];
            wmma::load_matrix_sync(a0, &sA[wr * ASTRH + k0], ASTRH);
            wmma::load_matrix_sync(a1, &sA[(wr + 16) * ASTRH + k0], ASTRH);
            #pragma unroll
            for (int j = 0; j < 4; j++)
                wmma::load_matrix_sync(b[j], &sW[k0 * WSTRH + wc + 16 * j], WSTRH);
            #pragma unroll
            for (int j = 0; j < 4; j++) {
                wmma::mma_sync(c[0][j], a0, b[j], c[0][j]);
                wmma::mma_sync(c[1][j], a1, b[j], c[1][j]);
            }
        }
        __syncthreads();           // all warps done reading sA

        // epilogue: four 32-row quarter-passes through the aliased fp32 C tile
        #pragma unroll
        for (int q = 0; q < 4; q++) {
            if (wr == q * 32) {
                #pragma unroll
                for (int i = 0; i < 2; i++)
                    #pragma unroll
                    for (int j = 0; j < 4; j++)
                        wmma::store_matrix_sync(&sC[(16 * i) * CSTR + wc + 16 * j],
                                                c[i][j], CSTR, wmma::mem_row_major);
            }
            __syncthreads();
            for (int i = t * 4; i < 32 * F; i += 256 * 4) {
                int r = i >> 7, k = i & 127;
                float4 v = *(const float4*)&sC[r * CSTR + k];
                __half2 h0 = __floats2half2_rn(v.x, v.y);
                __half2 h1 = __floats2half2_rn(v.z, v.w);
                uint2 u;
                u.x = *reinterpret_cast<unsigned*>(&h0);
                u.y = *reinterpret_cast<unsigned*>(&h1);
                *(uint2*)&g_half[(row0 + q * 32 + r) * F + k] = u;
            }
            __syncthreads();
        }
    }
}

// ---------------- Aggregation (software-pipelined, padded batches of 4) ----
__global__ void k_agg(const float* __restrict__ bias, int n) {
    int tid = blockIdx.x * blockDim.x + threadIdx.x;
    int hw = tid >> 4;
    int lane = tid & 15;
    int nhw = (gridDim.x * blockDim.x) >> 4;
    int fo = lane * 8;
    const __half* hl = g_half;
    const float4 bl = *(const float4*)&bias[fo];
    const float4 bh = *(const float4*)&bias[fo + 4];

    for (int nd = hw; nd < n; nd += nhw) {
        float dn = g_dinv[nd];
        float sw = dn * dn;
        float acc[8];
        {
            uint4 u = *(const uint4*)&hl[nd * F + fo];
            float2 p0 = __half22float2(*reinterpret_cast<__half2*>(&u.x));
            float2 p1 = __half22float2(*reinterpret_cast<__half2*>(&u.y));
            float2 p2 = __half22float2(*reinterpret_cast<__half2*>(&u.z));
            float2 p3 = __half22float2(*reinterpret_cast<__half2*>(&u.w));
            acc[0] = p0.x * sw; acc[1] = p0.y * sw;
            acc[2] = p1.x * sw; acc[3] = p1.y * sw;
            acc[4] = p2.x * sw; acc[5] = p2.y * sw;
            acc[6] = p3.x * sw; acc[7] = p3.y * sw;
        }
        int i = g_off[nd], iend = g_off[nd + 1];
        if (i < iend) {
            int2 e0 = g_ew[i], e1 = g_ew[i + 1], e2 = g_ew[i + 2], e3 = g_ew[i + 3];
            while (true) {
                uint4 u0 = *(const uint4*)&hl[e0.x * F + fo];
                uint4 u1 = *(const uint4*)&hl[e1.x * F + fo];
                uint4 u2 = *(const uint4*)&hl[e2.x * F + fo];
                uint4 u3 = *(const uint4*)&hl[e3.x * F + fo];
                i += 4;
                int2 f0 = g_ew[i], f1 = g_ew[i + 1], f2 = g_ew[i + 2], f3 = g_ew[i + 3];
                float w0 = __int_as_float(e0.y), w1 = __int_as_float(e1.y);
                float w2 = __int_as_float(e2.y), w3 = __int_as_float(e3.y);
                float2 a0 = __half22float2(*reinterpret_cast<__half2*>(&u0.x));
                float2 a1 = __half22float2(*reinterpret_cast<__half2*>(&u0.y));
                float2 a2 = __half22float2(*reinterpret_cast<__half2*>(&u0.z));
                float2 a3 = __half22float2(*reinterpret_cast<__half2*>(&u0.w));
                acc[0] = fmaf(a0.x, w0, acc[0]); acc[1] = fmaf(a0.y, w0, acc[1]);
                acc[2] = fmaf(a1.x, w0, acc[2]); acc[3] = fmaf(a1.y, w0, acc[3]);
                acc[4] = fmaf(a2.x, w0, acc[4]); acc[5] = fmaf(a2.y, w0, acc[5]);
                acc[6] = fmaf(a3.x, w0, acc[6]); acc[7] = fmaf(a3.y, w0, acc[7]);
                a0 = __half22float2(*reinterpret_cast<__half2*>(&u1.x));
                a1 = __half22float2(*reinterpret_cast<__half2*>(&u1.y));
                a2 = __half22float2(*reinterpret_cast<__half2*>(&u1.z));
                a3 = __half22float2(*reinterpret_cast<__half2*>(&u1.w));
                acc[0] = fmaf(a0.x, w1, acc[0]); acc[1] = fmaf(a0.y, w1, acc[1]);
                acc[2] = fmaf(a1.x, w1, acc[2]); acc[3] = fmaf(a1.y, w1, acc[3]);
                acc[4] = fmaf(a2.x, w1, acc[4]); acc[5] = fmaf(a2.y, w1, acc[5]);
                acc[6] = fmaf(a3.x, w1, acc[6]); acc[7] = fmaf(a3.y, w1, acc[7]);
                a0 = __half22float2(*reinterpret_cast<__half2*>(&u2.x));
                a1 = __half22float2(*reinterpret_cast<__half2*>(&u2.y));
                a2 = __half22float2(*reinterpret_cast<__half2*>(&u2.z));
                a3 = __half22float2(*reinterpret_cast<__half2*>(&u2.w));
                acc[0] = fmaf(a0.x, w2, acc[0]); acc[1] = fmaf(a0.y, w2, acc[1]);
                acc[2] = fmaf(a1.x, w2, acc[2]); acc[3] = fmaf(a1.y, w2, acc[3]);
                acc[4] = fmaf(a2.x, w2, acc[4]); acc[5] = fmaf(a2.y, w2, acc[5]);
                acc[6] = fmaf(a3.x, w2, acc[6]); acc[7] = fmaf(a3.y, w2, acc[7]);
                a0 = __half22float2(*reinterpret_cast<__half2*>(&u3.x));
                a1 = __half22float2(*reinterpret_cast<__half2*>(&u3.y));
                a2 = __half22float2(*reinterpret_cast<__half2*>(&u3.z));
                a3 = __half22float2(*reinterpret_cast<__half2*>(&u3.w));
                acc[0] = fmaf(a0.x, w3, acc[0]); acc[1] = fmaf(a0.y, w3, acc[1]);
                acc[2] = fmaf(a1.x, w3, acc[2]); acc[3] = fmaf(a1.y, w3, acc[3]);
                acc[4] = fmaf(a2.x, w3, acc[4]); acc[5] = fmaf(a2.y, w3, acc[5]);
                acc[6] = fmaf(a3.x, w3, acc[6]); acc[7] = fmaf(a3.y, w3, acc[7]);
                if (i >= iend) break;
                e0 = f0; e1 = f1; e2 = f2; e3 = f3;
            }
        }
        acc[0] = fmaxf(acc[0] + bl.x, 0.f); acc[1] = fmaxf(acc[1] + bl.y, 0.f);
        acc[2] = fmaxf(acc[2] + bl.z, 0.f); acc[3] = fmaxf(acc[3] + bl.w, 0.f);
        acc[4] = fmaxf(acc[4] + bh.x, 0.f); acc[5] = fmaxf(acc[5] + bh.y, 0.f);
        acc[6] = fmaxf(acc[6] + bh.z, 0.f); acc[7] = fmaxf(acc[7] + bh.w, 0.f);
        __half2 h0 = __floats2half2_rn(acc[0], acc[1]);
        __half2 h1 = __floats2half2_rn(acc[2], acc[3]);
        __half2 h2 = __floats2half2_rn(acc[4], acc[5]);
        __half2 h3 = __floats2half2_rn(acc[6], acc[7]);
        uint4 o;
        o.x = *reinterpret_cast<unsigned*>(&h0);
        o.y = *reinterpret_cast<unsigned*>(&h1);
        o.z = *reinterpret_cast<unsigned*>(&h2);
        o.w = *reinterpret_cast<unsigned*>(&h3);
        *(uint4*)&g_hin[nd * F + fo] = o;
    }
}

// ---------------- Pooling: 32 nodes per block --------
__global__ void k_pool(const int* __restrict__ batch, int n) {
    int f = threadIdx.x;
    int n0 = blockIdx.x * PCHUNK;
    if (n0 >= n) return;
    int n1 = min(n0 + PCHUNK, n);
    int cur = batch[n0];
    float m = 0.f;
    for (int nd = n0; nd < n1; nd++) {
        int gg = batch[nd];
        if (gg != cur) {
            atomicMax((int*)&g_pooled[cur * F + f], __float_as_int(m));
            cur = gg;
            m = 0.f;
        }
        m = fmaxf(m, __half2float(g_hin[nd * F + f]));
    }
    atomicMax((int*)&g_pooled[cur * F + f], __float_as_int(m));
}

// ---------------- Head ----------------
__global__ void k_head(const float* __restrict__ Wp1, const float* __restrict__ bp1,
                       const float* __restrict__ Wp2, const float* __restrict__ bp2,
                       float* __restrict__ out) {
    __shared__ float sp[F];
    __shared__ float t1[F];
    int t = threadIdx.x, g = blockIdx.x;
    sp[t] = g_pooled[g * F + t];
    __syncthreads();
    float a = bp1[t];
    #pragma unroll 4
    for (int k = 0; k < F; k++) a = fmaf(sp[k], Wp1[k * F + t], a);
    t1[t] = a;
    __syncthreads();
    if (t == 0) {
        float l0 = bp2[0], l1 = bp2[1];
        for (int k = 0; k < F; k++) {
            l0 = fmaf(t1[k], Wp2[2 * k], l0);
            l1 = fmaf(t1[k], Wp2[2 * k + 1], l1);
        }
        float m = fmaxf(l0, l1);
        float lse = m + logf(expf(l0 - m) + expf(l1 - m));
        out[2 * g] = l0 - lse;
        out[2 * g + 1] = l1 - lse;
    }
}

// ---------------- launch ----------------
extern "C" void kernel_launch(void* const* d_in, const int* in_sizes, int n_in,
                              void* d_out, int out_size) {
    const float* x   = (const float*)d_in[0];
    const int*   ei  = (const int*)d_in[1];
    const int*   bat = (const int*)d_in[2];
    const float* W1  = (const float*)d_in[3];  const float* b1  = (const float*)d_in[4];
    const float* W2  = (const float*)d_in[5];  const float* b2  = (const float*)d_in[6];
    const float* W3  = (const float*)d_in[7];  const float* b3  = (const float*)d_in[8];
    const float* Wp1 = (const float*)d_in[9];  const float* bp1 = (const float*)d_in[10];
    const float* Wp2 = (const float*)d_in[11]; const float* bp2 = (const float*)d_in[12];
    float* out = (float*)d_out;

    int n = in_sizes[0] / F;        // 100000
    int e = in_sizes[1] / 2;        // 1600000
    const int* src = ei;
    const int* dst = ei + e;

    cudaFuncSetAttribute(k_gemm_h, cudaFuncAttributeMaxDynamicSharedMemorySize, SMEM_TOTAL);

    k_zero<<<(NN + 255) / 256, 256>>>();                   // idx 0
    k_count<<<(e / 4 + 255) / 256, 256>>>(dst, e);         // idx 1 (vectorized)
    k_scan1<<<NBLK, CHUNK>>>(n);                           // idx 2
    k_gemm_h<<<296, 256, SMEM_TOTAL>>>(x, W1, n, 1);       // idx 3 <-- profiler target
    k_scan2<<<1, 256>>>(n);                                // idx 4
    k_scan3<<<NBLK, CHUNK>>>(n);                           // idx 5 (+pad)
    k_fill<<<(e + 255) / 256, 256>>>(src, dst, e);         // idx 6

    k_agg<<<1184, 256>>>(b1, n);
    k_gemm_h<<<296, 256, SMEM_TOTAL>>>(x, W2, n, 0);
    k_agg<<<1184, 256>>>(b2, n);
    k_gemm_h<<<296, 256, SMEM_TOTAL>>>(x, W3, n, 0);
    k_agg<<<1184, 256>>>(b3, n);

    k_pool<<<(n + PCHUNK - 1) / PCHUNK, F>>>(bat, n);
    k_head<<<G, F>>>(Wp1, bp1, Wp2, bp2, out);
}

// round 16
// speedup vs baseline: 1.0230x; 1.0087x over previous
#include <cuda_runtime.h>
#include <cuda_fp16.h>
#include <cuda_fp8.h>
#include <mma.h>
#include <math.h>

using namespace nvcuda;

#define NN 100000
#define NPAD (NN + 128)
#define EE 1600000
#define EWSZ (EE + 4 * NN + 8)
#define F  128
#define G  64
#define CHUNK 512
#define NBLK ((NN + CHUNK - 1) / CHUNK)   // 196
#define PCHUNK 32
#define WSTRH 136
#define ASTRH 136
#define CSTR  132

#define SW_BYTES (128 * WSTRH * 2)            // 34816
#define SA_BYTES (128 * ASTRH * 2)            // 34816
#define SMEM_TOTAL (SW_BYTES + SA_BYTES)      // 69632

// ---------------- device scratch (allocation-free) ----------------
__device__ unsigned char g_h8[NPAD * F]; // hl = h @ W, fp8 e4m3 (12.8 MB)
__device__ __half g_hin[NPAD * F];       // relu(agg) output, fp16
__device__ float  g_dinv[NN];
__device__ int    g_cnt[NN];
__device__ int    g_cur[NN];
__device__ int    g_off[NN + 1];
__device__ int2   g_ew[EWSZ];            // {src, norm weight bits}, padded + guard
__device__ int    g_bsum[NBLK];
__device__ int    g_bpre[NBLK];
__device__ float  g_pooled[G * F];

// ---------------- fp8 helpers ----------------
__device__ __forceinline__ unsigned pack4_e4m3(float4 v) {
    __nv_fp8x2_storage_t lo = __nv_cvt_float2_to_fp8x2(make_float2(v.x, v.y),
                                                       __NV_SATFINITE, __NV_E4M3);
    __nv_fp8x2_storage_t hi = __nv_cvt_float2_to_fp8x2(make_float2(v.z, v.w),
                                                       __NV_SATFINITE, __NV_E4M3);
    return (unsigned)lo | ((unsigned)hi << 16);
}

__device__ __forceinline__ void unpack8_e4m3(uint2 u, float* f) {
    __half2_raw r0 = __nv_cvt_fp8x2_to_halfraw2((__nv_fp8x2_storage_t)(u.x & 0xFFFFu), __NV_E4M3);
    __half2_raw r1 = __nv_cvt_fp8x2_to_halfraw2((__nv_fp8x2_storage_t)(u.x >> 16), __NV_E4M3);
    __half2_raw r2 = __nv_cvt_fp8x2_to_halfraw2((__nv_fp8x2_storage_t)(u.y & 0xFFFFu), __NV_E4M3);
    __half2_raw r3 = __nv_cvt_fp8x2_to_halfraw2((__nv_fp8x2_storage_t)(u.y >> 16), __NV_E4M3);
    float2 a;
    a = __half22float2(*reinterpret_cast<__half2*>(&r0)); f[0] = a.x; f[1] = a.y;
    a = __half22float2(*reinterpret_cast<__half2*>(&r1)); f[2] = a.x; f[3] = a.y;
    a = __half22float2(*reinterpret_cast<__half2*>(&r2)); f[4] = a.x; f[5] = a.y;
    a = __half22float2(*reinterpret_cast<__half2*>(&r3)); f[6] = a.x; f[7] = a.y;
}

// ---------------- setup: degree, dinv, padded CSR ----------------
__global__ void k_zero() {
    int i = blockIdx.x * blockDim.x + threadIdx.x;
    if (i < NN) { g_cnt[i] = 0; g_cur[i] = 0; }
    if (i < G * F) g_pooled[i] = 0.f;
}

__global__ void k_count(const int* __restrict__ dst, int e) {
    int i = (blockIdx.x * blockDim.x + threadIdx.x) * 4;
    if (i + 4 <= e) {
        int4 d = *(const int4*)&dst[i];
        atomicAdd(&g_cnt[d.x], 1);
        atomicAdd(&g_cnt[d.y], 1);
        atomicAdd(&g_cnt[d.z], 1);
        atomicAdd(&g_cnt[d.w], 1);
    } else {
        for (int j = i; j < e; j++) atomicAdd(&g_cnt[dst[j]], 1);
    }
}

__global__ void k_scan1(int n) {
    __shared__ int s[CHUNK];
    int t = threadIdx.x;
    int idx = blockIdx.x * CHUNK + t;
    int c = (idx < n) ? g_cnt[idx] : 0;
    if (idx < n) g_dinv[idx] = rsqrtf((float)(c + 1));   // +1 self loop
    s[t] = (c + 3) & ~3;
    __syncthreads();
    for (int o = CHUNK / 2; o > 0; o >>= 1) {
        if (t < o) s[t] += s[t + o];
        __syncthreads();
    }
    if (t == 0) g_bsum[blockIdx.x] = s[0];
}

__global__ void k_scan2(int n) {
    __shared__ int s[256];
    int t = threadIdx.x;
    int v = (t < NBLK) ? g_bsum[t] : 0;
    s[t] = v;
    __syncthreads();
    for (int o = 1; o < 256; o <<= 1) {
        int x = (t >= o) ? s[t - o] : 0;
        __syncthreads();
        s[t] += x;
        __syncthreads();
    }
    if (t < NBLK) g_bpre[t] = s[t] - v;
    if (t == 255) {
        g_off[n] = s[255];
        #pragma unroll
        for (int i = 0; i < 8; i++) g_ew[s[255] + i] = make_int2(0, 0);  // guard
    }
}

__global__ void k_scan3(int n) {
    __shared__ int s[CHUNK];
    int t = threadIdx.x;
    int idx = blockIdx.x * CHUNK + t;
    int cnt = (idx < n) ? g_cnt[idx] : 0;
    int v = (cnt + 3) & ~3;
    s[t] = v;
    __syncthreads();
    for (int o = 1; o < CHUNK; o <<= 1) {
        int x = (t >= o) ? s[t - o] : 0;
        __syncthreads();
        s[t] += x;
        __syncthreads();
    }
    if (idx < n) {
        int off = g_bpre[blockIdx.x] + s[t] - v;
        g_off[idx] = off;
        for (int p = off + cnt; p < off + v; p++) g_ew[p] = make_int2(0, 0);
    }
}

__global__ void k_fill(const int* __restrict__ src, const int* __restrict__ dst, int e) {
    int i = blockIdx.x * blockDim.x + threadIdx.x;
    if (i < e) {
        int d = dst[i];
        int s = src[i];
        int p = atomicAdd(&g_cur[d], 1);
        float w = g_dinv[s] * g_dinv[d];
        g_ew[g_off[d] + p] = make_int2(s, __float_as_int(w));
    }
}

// ---------------- GEMM (fp16 HMMA, fp32 acc): g_h8 = fp8(in @ W) ----------------
__global__ __launch_bounds__(256, 2)
void k_gemm_h(const float* __restrict__ xin, const float* __restrict__ W,
              int n, int first) {
    extern __shared__ char smraw[];
    __half* sW = (__half*)smraw;
    __half* sA = (__half*)(smraw + SW_BYTES);
    float*  sC = (float*)sA;       // alias, used after mainloop
    int t = threadIdx.x;

    for (int i = t * 2; i < F * F; i += 256 * 2) {
        int k = i >> 7, f = i & 127;
        __half2 h = __floats2half2_rn(W[i], W[i + 1]);
        *(__half2*)&sW[k * WSTRH + f] = h;
    }

    int warp = t >> 5;
    int wr = (warp & 3) * 32;
    int wc = (warp >> 2) * 64;
    int ntiles = (n + 127) >> 7;

    for (int tile = blockIdx.x; tile < ntiles; tile += gridDim.x) {
        int row0 = tile << 7;
        __syncthreads();
        if (first) {
            for (int i = t * 8; i < 128 * F; i += 256 * 8) {
                int r = i >> 7, k = i & 127;
                int rr = row0 + r;
                float4 v0 = make_float4(0.f, 0.f, 0.f, 0.f), v1 = v0;
                if (rr < n) {
                    v0 = *(const float4*)&xin[rr * F + k];
                    v1 = *(const float4*)&xin[rr * F + k + 4];
                }
                __half2 h0 = __floats2half2_rn(v0.x, v0.y);
                __half2 h1 = __floats2half2_rn(v0.z, v0.w);
                __half2 h2 = __floats2half2_rn(v1.x, v1.y);
                __half2 h3 = __floats2half2_rn(v1.z, v1.w);
                uint4 u;
                u.x = *reinterpret_cast<unsigned*>(&h0);
                u.y = *reinterpret_cast<unsigned*>(&h1);
                u.z = *reinterpret_cast<unsigned*>(&h2);
                u.w = *reinterpret_cast<unsigned*>(&h3);
                *(uint4*)&sA[r * ASTRH + k] = u;
            }
        } else {
            for (int i = t * 8; i < 128 * F; i += 256 * 8) {
                int r = i >> 7, k = i & 127;
                uint4 u = *(const uint4*)&g_hin[(row0 + r) * F + k];
                *(uint4*)&sA[r * ASTRH + k] = u;
            }
        }
        __syncthreads();

        wmma::fragment<wmma::accumulator, 16, 16, 16, float> c[2][4];
        #pragma unroll
        for (int i = 0; i < 2; i++)
            #pragma unroll
            for (int j = 0; j < 4; j++)
                wmma::fill_fragment(c[i][j], 0.f);

        #pragma unroll
        for (int k0 = 0; k0 < F; k0 += 16) {
            wmma::fragment<wmma::matrix_a, 16, 16, 16, __half, wmma::row_major> a0, a1;
            wmma::fragment<wmma::matrix_b, 16, 16, 16, __half, wmma::row_major> b[4];
            wmma::load_matrix_sync(a0, &sA[wr * ASTRH + k0], ASTRH);
            wmma::load_matrix_sync(a1, &sA[(wr + 16) * ASTRH + k0], ASTRH);
            #pragma unroll
            for (int j = 0; j < 4; j++)
                wmma::load_matrix_sync(b[j], &sW[k0 * WSTRH + wc + 16 * j], WSTRH);
            #pragma unroll
            for (int j = 0; j < 4; j++) {
                wmma::mma_sync(c[0][j], a0, b[j], c[0][j]);
                wmma::mma_sync(c[1][j], a1, b[j], c[1][j]);
            }
        }
        __syncthreads();

        // epilogue: four 32-row quarter-passes; pack fp32 -> fp8 e4m3
        #pragma unroll
        for (int q = 0; q < 4; q++) {
            if (wr == q * 32) {
                #pragma unroll
                for (int i = 0; i < 2; i++)
                    #pragma unroll
                    for (int j = 0; j < 4; j++)
                        wmma::store_matrix_sync(&sC[(16 * i) * CSTR + wc + 16 * j],
                                                c[i][j], CSTR, wmma::mem_row_major);
            }
            __syncthreads();
            for (int i = t * 4; i < 32 * F; i += 256 * 4) {
                int r = i >> 7, k = i & 127;
                float4 v = *(const float4*)&sC[r * CSTR + k];
                *(unsigned*)&g_h8[(row0 + q * 32 + r) * F + k] = pack4_e4m3(v);
            }
            __syncthreads();
        }
    }
}

// ---------------- Aggregation (fp8 gathers, fp32 accumulate) ----------------
// Half-warp (16 lanes) per node, lane owns 8 features (uint2 fp8 = 8B).
__global__ void k_agg(const float* __restrict__ bias, int n) {
    int tid = blockIdx.x * blockDim.x + threadIdx.x;
    int hw = tid >> 4;
    int lane = tid & 15;
    int nhw = (gridDim.x * blockDim.x) >> 4;
    int fo = lane * 8;
    const unsigned char* hl = g_h8;
    const float4 bl = *(const float4*)&bias[fo];
    const float4 bh = *(const float4*)&bias[fo + 4];

    for (int nd = hw; nd < n; nd += nhw) {
        float dn = g_dinv[nd];
        float sw = dn * dn;
        float acc[8];
        {
            uint2 u = *(const uint2*)&hl[nd * F + fo];
            float f[8];
            unpack8_e4m3(u, f);
            #pragma unroll
            for (int j = 0; j < 8; j++) acc[j] = f[j] * sw;
        }
        int i = g_off[nd], iend = g_off[nd + 1];   // padded: multiple of 4
        if (i < iend) {
            int2 e0 = g_ew[i], e1 = g_ew[i + 1], e2 = g_ew[i + 2], e3 = g_ew[i + 3];
            while (true) {
                uint2 u0 = *(const uint2*)&hl[e0.x * F + fo];
                uint2 u1 = *(const uint2*)&hl[e1.x * F + fo];
                uint2 u2 = *(const uint2*)&hl[e2.x * F + fo];
                uint2 u3 = *(const uint2*)&hl[e3.x * F + fo];
                i += 4;
                int2 f0 = g_ew[i], f1 = g_ew[i + 1], f2 = g_ew[i + 2], f3 = g_ew[i + 3];
                float w0 = __int_as_float(e0.y), w1 = __int_as_float(e1.y);
                float w2 = __int_as_float(e2.y), w3 = __int_as_float(e3.y);
                float v[8];
                unpack8_e4m3(u0, v);
                #pragma unroll
                for (int j = 0; j < 8; j++) acc[j] = fmaf(v[j], w0, acc[j]);
                unpack8_e4m3(u1, v);
                #pragma unroll
                for (int j = 0; j < 8; j++) acc[j] = fmaf(v[j], w1, acc[j]);
                unpack8_e4m3(u2, v);
                #pragma unroll
                for (int j = 0; j < 8; j++) acc[j] = fmaf(v[j], w2, acc[j]);
                unpack8_e4m3(u3, v);
                #pragma unroll
                for (int j = 0; j < 8; j++) acc[j] = fmaf(v[j], w3, acc[j]);
                if (i >= iend) break;
                e0 = f0; e1 = f1; e2 = f2; e3 = f3;
            }
        }
        acc[0] = fmaxf(acc[0] + bl.x, 0.f); acc[1] = fmaxf(acc[1] + bl.y, 0.f);
        acc[2] = fmaxf(acc[2] + bl.z, 0.f); acc[3] = fmaxf(acc[3] + bl.w, 0.f);
        acc[4] = fmaxf(acc[4] + bh.x, 0.f); acc[5] = fmaxf(acc[5] + bh.y, 0.f);
        acc[6] = fmaxf(acc[6] + bh.z, 0.f); acc[7] = fmaxf(acc[7] + bh.w, 0.f);
        __half2 h0 = __floats2half2_rn(acc[0], acc[1]);
        __half2 h1 = __floats2half2_rn(acc[2], acc[3]);
        __half2 h2 = __floats2half2_rn(acc[4], acc[5]);
        __half2 h3 = __floats2half2_rn(acc[6], acc[7]);
        uint4 o;
        o.x = *reinterpret_cast<unsigned*>(&h0);
        o.y = *reinterpret_cast<unsigned*>(&h1);
        o.z = *reinterpret_cast<unsigned*>(&h2);
        o.w = *reinterpret_cast<unsigned*>(&h3);
        *(uint4*)&g_hin[nd * F + fo] = o;
    }
}

// ---------------- Pooling: 32 nodes per block --------
__global__ void k_pool(const int* __restrict__ batch, int n) {
    int f = threadIdx.x;
    int n0 = blockIdx.x * PCHUNK;
    if (n0 >= n) return;
    int n1 = min(n0 + PCHUNK, n);
    int cur = batch[n0];
    float m = 0.f;
    for (int nd = n0; nd < n1; nd++) {
        int gg = batch[nd];
        if (gg != cur) {
            atomicMax((int*)&g_pooled[cur * F + f], __float_as_int(m));
            cur = gg;
            m = 0.f;
        }
        m = fmaxf(m, __half2float(g_hin[nd * F + f]));
    }
    atomicMax((int*)&g_pooled[cur * F + f], __float_as_int(m));
}

// ---------------- Head ----------------
__global__ void k_head(const float* __restrict__ Wp1, const float* __restrict__ bp1,
                       const float* __restrict__ Wp2, const float* __restrict__ bp2,
                       float* __restrict__ out) {
    __shared__ float sp[F];
    __shared__ float t1[F];
    int t = threadIdx.x, g = blockIdx.x;
    sp[t] = g_pooled[g * F + t];
    __syncthreads();
    float a = bp1[t];
    #pragma unroll 4
    for (int k = 0; k < F; k++) a = fmaf(sp[k], Wp1[k * F + t], a);
    t1[t] = a;
    __syncthreads();
    if (t == 0) {
        float l0 = bp2[0], l1 = bp2[1];
        for (int k = 0; k < F; k++) {
            l0 = fmaf(t1[k], Wp2[2 * k], l0);
            l1 = fmaf(t1[k], Wp2[2 * k + 1], l1);
        }
        float m = fmaxf(l0, l1);
        float lse = m + logf(expf(l0 - m) + expf(l1 - m));
        out[2 * g] = l0 - lse;
        out[2 * g + 1] = l1 - lse;
    }
}

// ---------------- launch ----------------
extern "C" void kernel_launch(void* const* d_in, const int* in_sizes, int n_in,
                              void* d_out, int out_size) {
    const float* x   = (const float*)d_in[0];
    const int*   ei  = (const int*)d_in[1];
    const int*   bat = (const int*)d_in[2];
    const float* W1  = (const float*)d_in[3];  const float* b1  = (const float*)d_in[4];
    const float* W2  = (const float*)d_in[5];  const float* b2  = (const float*)d_in[6];
    const float* W3  = (const float*)d_in[7];  const float* b3  = (const float*)d_in[8];
    const float* Wp1 = (const float*)d_in[9];  const float* bp1 = (const float*)d_in[10];
    const float* Wp2 = (const float*)d_in[11]; const float* bp2 = (const float*)d_in[12];
    float* out = (float*)d_out;

    int n = in_sizes[0] / F;        // 100000
    int e = in_sizes[1] / 2;        // 1600000
    const int* src = ei;
    const int* dst = ei + e;

    cudaFuncSetAttribute(k_gemm_h, cudaFuncAttributeMaxDynamicSharedMemorySize, SMEM_TOTAL);

    k_zero<<<(NN + 255) / 256, 256>>>();                   // idx 0
    k_count<<<(e / 4 + 255) / 256, 256>>>(dst, e);         // idx 1
    k_scan1<<<NBLK, CHUNK>>>(n);                           // idx 2
    k_gemm_h<<<296, 256, SMEM_TOTAL>>>(x, W1, n, 1);       // idx 3 <-- profiler target
    k_scan2<<<1, 256>>>(n);                                // idx 4
    k_scan3<<<NBLK, CHUNK>>>(n);                           // idx 5 (+pad)
    k_fill<<<(e + 255) / 256, 256>>>(src, dst, e);         // idx 6

    k_agg<<<1184, 256>>>(b1, n);
    k_gemm_h<<<296, 256, SMEM_TOTAL>>>(x, W2, n, 0);
    k_agg<<<1184, 256>>>(b2, n);
    k_gemm_h<<<296, 256, SMEM_TOTAL>>>(x, W3, n, 0);
    k_agg<<<1184, 256>>>(b3, n);

    k_pool<<<(n + PCHUNK - 1) / PCHUNK, F>>>(bat, n);
    k_head<<<G, F>>>(Wp1, bp1, Wp2, bp2, out);
}

// round 17
// speedup vs baseline: 1.0870x; 1.0626x over previous
#include <cuda_runtime.h>
#include <cuda_fp16.h>
#include <mma.h>
#include <math.h>

using namespace nvcuda;

#define NN 100000
#define NPAD (NN + 128)
#define EE 1600000
#define EWSZ (EE + 4 * NN + 8)
#define F  128
#define G  64
#define CHUNK 512
#define NBLK ((NN + CHUNK - 1) / CHUNK)   // 196
#define PCHUNK 32
#define WSTRH 136
#define ASTRH 136
#define CSTR  132

#define SW_BYTES (128 * WSTRH * 2)            // 34816
#define SA_BYTES (128 * ASTRH * 2)            // 34816
#define SMEM_TOTAL (SW_BYTES + SA_BYTES)      // 69632

// ---------------- device scratch (allocation-free) ----------------
__device__ __half g_half[NPAD * F];  // hl = h @ W, fp16
__device__ __half g_hin[NPAD * F];   // relu(agg) output, fp16
__device__ float  g_dinv[NN];
__device__ int    g_cnt[NN];
__device__ int    g_cur[NN];
__device__ int    g_off[NN + 1];
__device__ int2   g_ew[EWSZ];        // {src, norm weight bits}, padded + guard
__device__ int    g_bsum[NBLK];
__device__ int    g_bpre[NBLK];
__device__ float  g_pooled[G * F];

// ---------------- setup: degree, dinv, padded CSR ----------------
__global__ void k_zero() {
    int i = blockIdx.x * blockDim.x + threadIdx.x;
    if (i < NN) { g_cnt[i] = 0; g_cur[i] = 0; }
    if (i < G * F) g_pooled[i] = 0.f;
}

__global__ void k_count(const int* __restrict__ dst, int e) {
    int i = (blockIdx.x * blockDim.x + threadIdx.x) * 4;
    if (i + 4 <= e) {
        int4 d = *(const int4*)&dst[i];
        atomicAdd(&g_cnt[d.x], 1);
        atomicAdd(&g_cnt[d.y], 1);
        atomicAdd(&g_cnt[d.z], 1);
        atomicAdd(&g_cnt[d.w], 1);
    } else {
        for (int j = i; j < e; j++) atomicAdd(&g_cnt[dst[j]], 1);
    }
}

__global__ void k_scan1(int n) {
    __shared__ int s[CHUNK];
    int t = threadIdx.x;
    int idx = blockIdx.x * CHUNK + t;
    int c = (idx < n) ? g_cnt[idx] : 0;
    if (idx < n) g_dinv[idx] = rsqrtf((float)(c + 1));   // +1 self loop
    s[t] = (c + 3) & ~3;
    __syncthreads();
    for (int o = CHUNK / 2; o > 0; o >>= 1) {
        if (t < o) s[t] += s[t + o];
        __syncthreads();
    }
    if (t == 0) g_bsum[blockIdx.x] = s[0];
}

__global__ void k_scan2(int n) {
    __shared__ int s[256];
    int t = threadIdx.x;
    int v = (t < NBLK) ? g_bsum[t] : 0;
    s[t] = v;
    __syncthreads();
    for (int o = 1; o < 256; o <<= 1) {
        int x = (t >= o) ? s[t - o] : 0;
        __syncthreads();
        s[t] += x;
        __syncthreads();
    }
    if (t < NBLK) g_bpre[t] = s[t] - v;
    if (t == 255) {
        g_off[n] = s[255];
        #pragma unroll
        for (int i = 0; i < 8; i++) g_ew[s[255] + i] = make_int2(0, 0);  // guard
    }
}

__global__ void k_scan3(int n) {
    __shared__ int s[CHUNK];
    int t = threadIdx.x;
    int idx = blockIdx.x * CHUNK + t;
    int cnt = (idx < n) ? g_cnt[idx] : 0;
    int v = (cnt + 3) & ~3;
    s[t] = v;
    __syncthreads();
    for (int o = 1; o < CHUNK; o <<= 1) {
        int x = (t >= o) ? s[t - o] : 0;
        __syncthreads();
        s[t] += x;
        __syncthreads();
    }
    if (idx < n) {
        int off = g_bpre[blockIdx.x] + s[t] - v;
        g_off[idx] = off;
        for (int p = off + cnt; p < off + v; p++) g_ew[p] = make_int2(0, 0);
    }
}

__global__ void k_fill(const int* __restrict__ src, const int* __restrict__ dst, int e) {
    int i = blockIdx.x * blockDim.x + threadIdx.x;
    if (i < e) {
        int d = dst[i];
        int s = src[i];
        int p = atomicAdd(&g_cur[d], 1);
        float w = g_dinv[s] * g_dinv[d];
        g_ew[g_off[d] + p] = make_int2(s, __float_as_int(w));
    }
}

// ---------------- GEMM (fp16 HMMA, fp32 acc): g_half = in @ W ----------------
__global__ __launch_bounds__(256, 2)
void k_gemm_h(const float* __restrict__ xin, const float* __restrict__ W,
              int n, int first) {
    extern __shared__ char smraw[];
    __half* sW = (__half*)smraw;
    __half* sA = (__half*)(smraw + SW_BYTES);
    float*  sC = (float*)sA;       // alias, used after mainloop
    int t = threadIdx.x;

    for (int i = t * 2; i < F * F; i += 256 * 2) {
        int k = i >> 7, f = i & 127;
        __half2 h = __floats2half2_rn(W[i], W[i + 1]);
        *(__half2*)&sW[k * WSTRH + f] = h;
    }

    int warp = t >> 5;
    int wr = (warp & 3) * 32;
    int wc = (warp >> 2) * 64;
    int ntiles = (n + 127) >> 7;

    for (int tile = blockIdx.x; tile < ntiles; tile += gridDim.x) {
        int row0 = tile << 7;
        __syncthreads();
        if (first) {
            for (int i = t * 8; i < 128 * F; i += 256 * 8) {
                int r = i >> 7, k = i & 127;
                int rr = row0 + r;
                float4 v0 = make_float4(0.f, 0.f, 0.f, 0.f), v1 = v0;
                if (rr < n) {
                    v0 = *(const float4*)&xin[rr * F + k];
                    v1 = *(const float4*)&xin[rr * F + k + 4];
                }
                __half2 h0 = __floats2half2_rn(v0.x, v0.y);
                __half2 h1 = __floats2half2_rn(v0.z, v0.w);
                __half2 h2 = __floats2half2_rn(v1.x, v1.y);
                __half2 h3 = __floats2half2_rn(v1.z, v1.w);
                uint4 u;
                u.x = *reinterpret_cast<unsigned*>(&h0);
                u.y = *reinterpret_cast<unsigned*>(&h1);
                u.z = *reinterpret_cast<unsigned*>(&h2);
                u.w = *reinterpret_cast<unsigned*>(&h3);
                *(uint4*)&sA[r * ASTRH + k] = u;
            }
        } else {
            for (int i = t * 8; i < 128 * F; i += 256 * 8) {
                int r = i >> 7, k = i & 127;
                uint4 u = *(const uint4*)&g_hin[(row0 + r) * F + k];
                *(uint4*)&sA[r * ASTRH + k] = u;
            }
        }
        __syncthreads();

        wmma::fragment<wmma::accumulator, 16, 16, 16, float> c[2][4];
        #pragma unroll
        for (int i = 0; i < 2; i++)
            #pragma unroll
            for (int j = 0; j < 4; j++)
                wmma::fill_fragment(c[i][j], 0.f);

        #pragma unroll
        for (int k0 = 0; k0 < F; k0 += 16) {
            wmma::fragment<wmma::matrix_a, 16, 16, 16, __half, wmma::row_major> a0, a1;
            wmma::fragment<wmma::matrix_b, 16, 16, 16, __half, wmma::row_major> b[4];
            wmma::load_matrix_sync(a0, &sA[wr * ASTRH + k0], ASTRH);
            wmma::load_matrix_sync(a1, &sA[(wr + 16) * ASTRH + k0], ASTRH);
            #pragma unroll
            for (int j = 0; j < 4; j++)
                wmma::load_matrix_sync(b[j], &sW[k0 * WSTRH + wc + 16 * j], WSTRH);
            #pragma unroll
            for (int j = 0; j < 4; j++) {
                wmma::mma_sync(c[0][j], a0, b[j], c[0][j]);
                wmma::mma_sync(c[1][j], a1, b[j], c[1][j]);
            }
        }
        __syncthreads();

        #pragma unroll
        for (int q = 0; q < 4; q++) {
            if (wr == q * 32) {
                #pragma unroll
                for (int i = 0; i < 2; i++)
                    #pragma unroll
                    for (int j = 0; j < 4; j++)
                        wmma::store_matrix_sync(&sC[(16 * i) * CSTR + wc + 16 * j],
                                                c[i][j], CSTR, wmma::mem_row_major);
            }
            __syncthreads();
            for (int i = t * 4; i < 32 * F; i += 256 * 4) {
                int r = i >> 7, k = i & 127;
                float4 v = *(const float4*)&sC[r * CSTR + k];
                __half2 h0 = __floats2half2_rn(v.x, v.y);
                __half2 h1 = __floats2half2_rn(v.z, v.w);
                uint2 u;
                u.x = *reinterpret_cast<unsigned*>(&h0);
                u.y = *reinterpret_cast<unsigned*>(&h1);
                *(uint2*)&g_half[(row0 + q * 32 + r) * F + k] = u;
            }
            __syncthreads();
        }
    }
}

// ---------------- Aggregation (half2 HFMA2 accumulate, ~6 ops/edge/lane) ----
// Half-warp per node, lane owns 8 features (uint4 fp16). acc in 4x __half2.
__global__ void k_agg(const float* __restrict__ bias, int n) {
    int tid = blockIdx.x * blockDim.x + threadIdx.x;
    int hw = tid >> 4;
    int lane = tid & 15;
    int nhw = (gridDim.x * blockDim.x) >> 4;
    int fo = lane * 8;
    const __half* hl = g_half;
    const float4 bl = *(const float4*)&bias[fo];
    const float4 bh = *(const float4*)&bias[fo + 4];

    for (int nd = hw; nd < n; nd += nhw) {
        float dn = g_dinv[nd];
        __half2 acc0, acc1, acc2, acc3;
        {
            __half2 swh = __float2half2_rn(dn * dn);
            uint4 u = *(const uint4*)&hl[nd * F + fo];
            acc0 = __hmul2(*reinterpret_cast<__half2*>(&u.x), swh);
            acc1 = __hmul2(*reinterpret_cast<__half2*>(&u.y), swh);
            acc2 = __hmul2(*reinterpret_cast<__half2*>(&u.z), swh);
            acc3 = __hmul2(*reinterpret_cast<__half2*>(&u.w), swh);
        }
        int i = g_off[nd], iend = g_off[nd + 1];   // padded: multiple of 4
        if (i < iend) {
            int2 e0 = g_ew[i], e1 = g_ew[i + 1], e2 = g_ew[i + 2], e3 = g_ew[i + 3];
            while (true) {
                uint4 u0 = *(const uint4*)&hl[e0.x * F + fo];
                uint4 u1 = *(const uint4*)&hl[e1.x * F + fo];
                uint4 u2 = *(const uint4*)&hl[e2.x * F + fo];
                uint4 u3 = *(const uint4*)&hl[e3.x * F + fo];
                i += 4;
                int2 f0 = g_ew[i], f1 = g_ew[i + 1], f2 = g_ew[i + 2], f3 = g_ew[i + 3];
                __half2 w0 = __float2half2_rn(__int_as_float(e0.y));
                __half2 w1 = __float2half2_rn(__int_as_float(e1.y));
                __half2 w2 = __float2half2_rn(__int_as_float(e2.y));
                __half2 w3 = __float2half2_rn(__int_as_float(e3.y));
                acc0 = __hfma2(*reinterpret_cast<__half2*>(&u0.x), w0, acc0);
                acc1 = __hfma2(*reinterpret_cast<__half2*>(&u0.y), w0, acc1);
                acc2 = __hfma2(*reinterpret_cast<__half2*>(&u0.z), w0, acc2);
                acc3 = __hfma2(*reinterpret_cast<__half2*>(&u0.w), w0, acc3);
                acc0 = __hfma2(*reinterpret_cast<__half2*>(&u1.x), w1, acc0);
                acc1 = __hfma2(*reinterpret_cast<__half2*>(&u1.y), w1, acc1);
                acc2 = __hfma2(*reinterpret_cast<__half2*>(&u1.z), w1, acc2);
                acc3 = __hfma2(*reinterpret_cast<__half2*>(&u1.w), w1, acc3);
                acc0 = __hfma2(*reinterpret_cast<__half2*>(&u2.x), w2, acc0);
                acc1 = __hfma2(*reinterpret_cast<__half2*>(&u2.y), w2, acc1);
                acc2 = __hfma2(*reinterpret_cast<__half2*>(&u2.z), w2, acc2);
                acc3 = __hfma2(*reinterpret_cast<__half2*>(&u2.w), w2, acc3);
                acc0 = __hfma2(*reinterpret_cast<__half2*>(&u3.x), w3, acc0);
                acc1 = __hfma2(*reinterpret_cast<__half2*>(&u3.y), w3, acc1);
                acc2 = __hfma2(*reinterpret_cast<__half2*>(&u3.z), w3, acc2);
                acc3 = __hfma2(*reinterpret_cast<__half2*>(&u3.w), w3, acc3);
                if (i >= iend) break;
                e0 = f0; e1 = f1; e2 = f2; e3 = f3;
            }
        }
        // unpack -> fp32 bias + relu -> fp16 store
        float2 p0 = __half22float2(acc0);
        float2 p1 = __half22float2(acc1);
        float2 p2 = __half22float2(acc2);
        float2 p3 = __half22float2(acc3);
        float a0 = fmaxf(p0.x + bl.x, 0.f), a1 = fmaxf(p0.y + bl.y, 0.f);
        float a2 = fmaxf(p1.x + bl.z, 0.f), a3 = fmaxf(p1.y + bl.w, 0.f);
        float a4 = fmaxf(p2.x + bh.x, 0.f), a5 = fmaxf(p2.y + bh.y, 0.f);
        float a6 = fmaxf(p3.x + bh.z, 0.f), a7 = fmaxf(p3.y + bh.w, 0.f);
        __half2 h0 = __floats2half2_rn(a0, a1);
        __half2 h1 = __floats2half2_rn(a2, a3);
        __half2 h2 = __floats2half2_rn(a4, a5);
        __half2 h3 = __floats2half2_rn(a6, a7);
        uint4 o;
        o.x = *reinterpret_cast<unsigned*>(&h0);
        o.y = *reinterpret_cast<unsigned*>(&h1);
        o.z = *reinterpret_cast<unsigned*>(&h2);
        o.w = *reinterpret_cast<unsigned*>(&h3);
        *(uint4*)&g_hin[nd * F + fo] = o;
    }
}

// ---------------- Pooling: 32 nodes per block --------
__global__ void k_pool(const int* __restrict__ batch, int n) {
    int f = threadIdx.x;
    int n0 = blockIdx.x * PCHUNK;
    if (n0 >= n) return;
    int n1 = min(n0 + PCHUNK, n);
    int cur = batch[n0];
    float m = 0.f;
    for (int nd = n0; nd < n1; nd++) {
        int gg = batch[nd];
        if (gg != cur) {
            atomicMax((int*)&g_pooled[cur * F + f], __float_as_int(m));
            cur = gg;
            m = 0.f;
        }
        m = fmaxf(m, __half2float(g_hin[nd * F + f]));
    }
    atomicMax((int*)&g_pooled[cur * F + f], __float_as_int(m));
}

// ---------------- Head ----------------
__global__ void k_head(const float* __restrict__ Wp1, const float* __restrict__ bp1,
                       const float* __restrict__ Wp2, const float* __restrict__ bp2,
                       float* __restrict__ out) {
    __shared__ float sp[F];
    __shared__ float t1[F];
    int t = threadIdx.x, g = blockIdx.x;
    sp[t] = g_pooled[g * F + t];
    __syncthreads();
    float a = bp1[t];
    #pragma unroll 4
    for (int k = 0; k < F; k++) a = fmaf(sp[k], Wp1[k * F + t], a);
    t1[t] = a;
    __syncthreads();
    if (t == 0) {
        float l0 = bp2[0], l1 = bp2[1];
        for (int k = 0; k < F; k++) {
            l0 = fmaf(t1[k], Wp2[2 * k], l0);
            l1 = fmaf(t1[k], Wp2[2 * k + 1], l1);
        }
        float m = fmaxf(l0, l1);
        float lse = m + logf(expf(l0 - m) + expf(l1 - m));
        out[2 * g] = l0 - lse;
        out[2 * g + 1] = l1 - lse;
    }
}

// ---------------- launch ----------------
extern "C" void kernel_launch(void* const* d_in, const int* in_sizes, int n_in,
                              void* d_out, int out_size) {
    const float* x   = (const float*)d_in[0];
    const int*   ei  = (const int*)d_in[1];
    const int*   bat = (const int*)d_in[2];
    const float* W1  = (const float*)d_in[3];  const float* b1  = (const float*)d_in[4];
    const float* W2  = (const float*)d_in[5];  const float* b2  = (const float*)d_in[6];
    const float* W3  = (const float*)d_in[7];  const float* b3  = (const float*)d_in[8];
    const float* Wp1 = (const float*)d_in[9];  const float* bp1 = (const float*)d_in[10];
    const float* Wp2 = (const float*)d_in[11]; const float* bp2 = (const float*)d_in[12];
    float* out = (float*)d_out;

    int n = in_sizes[0] / F;        // 100000
    int e = in_sizes[1] / 2;        // 1600000
    const int* src = ei;
    const int* dst = ei + e;

    cudaFuncSetAttribute(k_gemm_h, cudaFuncAttributeMaxDynamicSharedMemorySize, SMEM_TOTAL);

    k_zero<<<(NN + 255) / 256, 256>>>();                   // idx 0
    k_count<<<(e / 4 + 255) / 256, 256>>>(dst, e);         // idx 1
    k_scan1<<<NBLK, CHUNK>>>(n);                           // idx 2
    k_gemm_h<<<296, 256, SMEM_TOTAL>>>(x, W1, n, 1);       // idx 3 <-- profiler target
    k_scan2<<<1, 256>>>(n);                                // idx 4
    k_scan3<<<NBLK, CHUNK>>>(n);                           // idx 5 (+pad)
    k_fill<<<(e + 255) / 256, 256>>>(src, dst, e);         // idx 6

    k_agg<<<1184, 256>>>(b1, n);
    k_gemm_h<<<296, 256, SMEM_TOTAL>>>(x, W2, n, 0);
    k_agg<<<1184, 256>>>(b2, n);
    k_gemm_h<<<296, 256, SMEM_TOTAL>>>(x, W3, n, 0);
    k_agg<<<1184, 256>>>(b3, n);

    k_pool<<<(n + PCHUNK - 1) / PCHUNK, F>>>(bat, n);
    k_head<<<G, F>>>(Wp1, bp1, Wp2, bp2, out);
}